// round 2
// baseline (speedup 1.0000x reference)
#include <cuda_runtime.h>

#define TINYV 1.1920929e-7f   // float32 machine epsilon, matches np.finfo(float32).eps

// custom_round(x) = floor(x - sign(x)*TINY + 0.5), sign(0) = 0
__device__ __forceinline__ float cround(float x) {
    float s = (x > 0.0f) ? TINYV : ((x < 0.0f) ? -TINYV : 0.0f);
    return floorf((x - s) + 0.5f);
}

// closest point in E8 = D8 union (D8 + 1/2), replicating the reference
// (g_x tie-break: first index of max |x - round(x)|; final tie d0==d1 -> y1)
__device__ __forceinline__ void cp_e8(const float x[8], float y[8]) {
    // ---- branch 0: D8 ----
    float f[8];
    float s0 = 0.0f;
#pragma unroll
    for (int j = 0; j < 8; j++) { f[j] = cround(x[j]); s0 += f[j]; }
    bool odd0 = (((int)s0) & 1) != 0;

    float bestd = -1.0f, xk = 0.0f, fk = 0.0f; int k0 = 0;
#pragma unroll
    for (int j = 0; j < 8; j++) {
        float d = fabsf(x[j] - f[j]);
        if (d > bestd) { bestd = d; k0 = j; xk = x[j]; fk = f[j]; }
    }
    float step0 = (xk >= 0.0f) ? ((fk < xk) ? 1.0f : -1.0f)
                               : ((fk <= xk) ? 1.0f : -1.0f);

    // ---- branch 1: D8 + 1/2 ----
    float xs[8], fs[8];
    float s1 = 0.0f;
#pragma unroll
    for (int j = 0; j < 8; j++) {
        xs[j] = x[j] - 0.5f;
        fs[j] = cround(xs[j]);
        s1 += fs[j];
    }
    bool odd1 = (((int)s1) & 1) != 0;

    float bestd1 = -1.0f, xk1 = 0.0f, fk1 = 0.0f; int k1 = 0;
#pragma unroll
    for (int j = 0; j < 8; j++) {
        float d = fabsf(xs[j] - fs[j]);
        if (d > bestd1) { bestd1 = d; k1 = j; xk1 = xs[j]; fk1 = fs[j]; }
    }
    float step1 = (xk1 >= 0.0f) ? ((fk1 < xk1) ? 1.0f : -1.0f)
                                : ((fk1 <= xk1) ? 1.0f : -1.0f);

    // ---- assemble candidates + distances ----
    float d0 = 0.0f, d1 = 0.0f;
    float y0[8], y1[8];
#pragma unroll
    for (int j = 0; j < 8; j++) {
        float a0 = f[j]  + ((odd0 && j == k0) ? step0 : 0.0f);
        float a1 = (fs[j] + ((odd1 && j == k1) ? step1 : 0.0f)) + 0.5f;
        y0[j] = a0; y1[j] = a1;
        float r0 = x[j] - a0;
        float r1 = x[j] - a1;
        d0 += r0 * r0;
        d1 += r1 * r1;
    }
    bool pick0 = (d0 < d1);   // tie -> y1, matching jnp.where(d0 < d1, y0, y1)
#pragma unroll
    for (int j = 0; j < 8; j++) y[j] = pick0 ? y0[j] : y1[j];
}

__global__ __launch_bounds__(128)
void LatticeQuantizer_kernel(const float* __restrict__ x,
                             const float* __restrict__ beta_p,
                             const float* __restrict__ G,
                             const float* __restrict__ Ginv,
                             const float* __restrict__ eps,
                             float* __restrict__ out, int N)
{
    __shared__ float sG[64], sGi[64], sE[8], sBeta;
    int t = threadIdx.x;
    if (t < 64) { sG[t] = G[t]; sGi[t] = Ginv[t]; }
    if (t < 8)  sE[t] = eps[t];
    if (t == 0) sBeta = beta_p[0];
    __syncthreads();

    int i = blockIdx.x * blockDim.x + threadIdx.x;
    if (i >= N) return;

    float4 va = ((const float4*)x)[2 * i];
    float4 vb = ((const float4*)x)[2 * i + 1];
    float xl[8] = {va.x, va.y, va.z, va.w, vb.x, vb.y, vb.z, vb.w};
    float beta = sBeta;
#pragma unroll
    for (int j = 0; j < 8; j++) xl[j] = __fdiv_rn(xl[j], beta);  // IEEE div regardless of fast_math

    float xh[8] = {0, 0, 0, 0, 0, 0, 0, 0};
    float scale = 1.0f;

#pragma unroll
    for (int m = 0; m < 3; m++) {
        // encode: x_l = closest_point_E8(x_l + eps)
        float xe[8], yq[8];
#pragma unroll
        for (int j = 0; j < 8; j++) xe[j] = xl[j] + sE[j];
        cp_e8(xe, yq);

        // b = custom_round(fmod(yq @ G_inv, 4))
        float bv[8];
#pragma unroll
        for (int j = 0; j < 8; j++) {
            float acc = 0.0f;
#pragma unroll
            for (int q = 0; q < 8; q++) acc += yq[q] * sGi[q * 8 + j];
            float r = acc - 4.0f * truncf(acc * 0.25f);   // == fmodf(acc, 4) exactly here
            bv[j] = cround(r);
        }

        // next layer input
#pragma unroll
        for (int j = 0; j < 8; j++) xl[j] = yq[j] * 0.25f;

        // decode (fused): Gb = b @ G.T ; x_i = Gb - 4*cp_e8(Gb/4) ; xh += 4^m * x_i
        float gb[8], gq[8], cpv[8];
#pragma unroll
        for (int j = 0; j < 8; j++) {
            float acc = 0.0f;
#pragma unroll
            for (int q = 0; q < 8; q++) acc += bv[q] * sG[j * 8 + q];
            gb[j] = acc;
            gq[j] = acc * 0.25f;
        }
        cp_e8(gq, cpv);
#pragma unroll
        for (int j = 0; j < 8; j++) xh[j] += scale * (gb[j] - 4.0f * cpv[j]);
        scale *= 4.0f;
    }

    float4 o0, o1;
    o0.x = beta * xh[0]; o0.y = beta * xh[1]; o0.z = beta * xh[2]; o0.w = beta * xh[3];
    o1.x = beta * xh[4]; o1.y = beta * xh[5]; o1.z = beta * xh[6]; o1.w = beta * xh[7];
    ((float4*)out)[2 * i]     = o0;
    ((float4*)out)[2 * i + 1] = o1;
}

extern "C" void kernel_launch(void* const* d_in, const int* in_sizes, int n_in,
                              void* d_out, int out_size) {
    const float* x    = (const float*)d_in[0];
    const float* beta = (const float*)d_in[1];
    const float* G    = (const float*)d_in[2];
    const float* Gi   = (const float*)d_in[3];
    const float* eps  = (const float*)d_in[4];
    float* out = (float*)d_out;

    int N = in_sizes[0] / 8;
    int threads = 128;
    int blocks = (N + threads - 1) / threads;
    LatticeQuantizer_kernel<<<blocks, threads>>>(x, beta, G, Gi, eps, out, N);
}

// round 4
// speedup vs baseline: 2.1738x; 2.1738x over previous
#include <cuda_runtime.h>

#define TINYV 1.1920929e-7f   // float32 machine eps, matches np.finfo(float32).eps

// custom_round(x) = floor(x - sign(x)*TINY + 0.5).
// copysign(TINY,x) differs from sign(x)*TINY only at x==+-0, where both yield 0.
__device__ __forceinline__ float cround(float x) {
    return floorf((x - copysignf(TINYV, x)) + 0.5f);
}

// One candidate branch of closest_point_E8:
//   xa  = shifted input (x or x-0.5) on which rounding/g_x runs
//   xo  = original input (distance measured against this)
//   half = 0.0 or 0.5 added to the candidate at the end
// Writes candidate into yc[8], returns d = sum_j (xo_j - yc_j)^2 (sequential order).
__device__ __forceinline__ float e8_branch(const float xa[8], const float xo[8],
                                           float half, float yc[8]) {
    float f[8], e[8];
#pragma unroll
    for (int j = 0; j < 8; j++) { f[j] = cround(xa[j]); e[j] = xa[j] - f[j]; }

    // parity of sum(f) (small exact integers -> any summation order)
    float sum = ((f[0] + f[1]) + (f[2] + f[3])) + ((f[4] + f[5]) + (f[6] + f[7]));
    bool odd = (((int)sum) & 1) != 0;

    // max |e| (FMNMX absorbs |.| as operand modifier)
    float m = fmaxf(fmaxf(fmaxf(fabsf(e[0]), fabsf(e[1])), fmaxf(fabsf(e[2]), fabsf(e[3]))),
                    fmaxf(fmaxf(fabsf(e[4]), fabsf(e[5])), fmaxf(fabsf(e[6]), fabsf(e[7]))));

    // first index attaining the max (matches jnp.argmax first-occurrence)
    bool sel[8];
    bool seen = false;
#pragma unroll
    for (int j = 0; j < 8; j++) {
        bool eq = (fabsf(e[j]) == m);
        sel[j] = eq && !seen;
        seen = seen || eq;
    }

    // gather e at the selected index
    float t = e[0];
#pragma unroll
    for (int j = 1; j < 8; j++) t = sel[j] ? e[j] : t;
    // all-integer row (m==0): k=0, reference step rule == copysign(1, -xa[0])
    t = (m == 0.0f) ? -xa[0] : t;
    // for e_k != 0 the reference step rule reduces exactly to sign(e_k)
    float step = copysignf(1.0f, t);

#pragma unroll
    for (int j = 0; j < 8; j++) {
        float base = f[j] + half;                       // exact: f integer, half in {0,.5}
        yc[j] = (odd && sel[j]) ? (base + step) : base; // matches (f + onehot*step) + half
    }

    // distance vs ORIGINAL x, sequential accumulation (same order as reference/R1)
    float r = xo[0] - yc[0];
    float d = r * r;
#pragma unroll
    for (int j = 1; j < 8; j++) { r = xo[j] - yc[j]; d = fmaf(r, r, d); }
    return d;
}

__device__ __forceinline__ void cp_e8(const float x[8], float y[8]) {
    float yA[8], yB[8], xs[8];
    float dA = e8_branch(x, x, 0.0f, yA);
#pragma unroll
    for (int j = 0; j < 8; j++) xs[j] = x[j] - 0.5f;
    float dB = e8_branch(xs, x, 0.5f, yB);
    bool pickA = dA < dB;   // tie -> B, matching jnp.where(d0 < d1, y0, y1)
#pragma unroll
    for (int j = 0; j < 8; j++) y[j] = pickA ? yA[j] : yB[j];
}

__global__ __launch_bounds__(128)
void LatticeQuantizer_kernel(const float* __restrict__ x,
                             const float* __restrict__ beta_p,
                             const float* __restrict__ eps,
                             float* __restrict__ out, int N)
{
    int i = blockIdx.x * blockDim.x + threadIdx.x;
    if (i >= N) return;

    float beta = __ldg(beta_p);
    float4 e0 = __ldg((const float4*)eps);
    float4 e1 = __ldg((const float4*)eps + 1);
    float ev[8] = {e0.x, e0.y, e0.z, e0.w, e1.x, e1.y, e1.z, e1.w};

    float4 va = ((const float4*)x)[2 * i];
    float4 vb = ((const float4*)x)[2 * i + 1];
    float xl[8] = {va.x, va.y, va.z, va.w, vb.x, vb.y, vb.z, vb.w};
#pragma unroll
    for (int j = 0; j < 8; j++) xl[j] = __fdiv_rn(xl[j], beta);  // IEEE div under fast_math

    float xh[8];

#pragma unroll
    for (int m = 0; m < 3; m++) {
        // ---- encode: yq = closest_point_E8(xl + eps) ----
        float xe[8], yq[8];
#pragma unroll
        for (int j = 0; j < 8; j++) xe[j] = xl[j] + ev[j];
        cp_e8(xe, yq);

        // ---- acc = yq @ G_inv via exact forward substitution (acc @ Gm = yq) ----
        // a0 = y0/2; a_j = a_{j-1} + y_j (j=1..6); a7 = 2*y7 - sum(a0..a6).
        // All intermediates are exact dyadics (quarter-integer grid) -> bit-equal
        // to the dense matmul with the dyadic G_inv entries.
        float a[8];
        a[0] = 0.5f * yq[0];
#pragma unroll
        for (int j = 1; j < 7; j++) a[j] = a[j - 1] + yq[j];
        float s06 = ((a[0] + a[1]) + (a[2] + a[3])) + ((a[4] + a[5]) + a[6]);
        a[7] = fmaf(2.0f, yq[7], -s06);

        // ---- b = custom_round(fmod(acc, 4)) ----
        // acc may be QUARTER-integer (half-coset encode points) -> cround is REQUIRED.
        // trunc-form fmod is exact on this dyadic grid.
        float bv[8];
#pragma unroll
        for (int j = 0; j < 8; j++) {
            float r = a[j] - 4.0f * truncf(a[j] * 0.25f);   // == fmodf(a, 4) exactly
            bv[j] = cround(r);
        }

        // ---- next layer input ----
#pragma unroll
        for (int j = 0; j < 8; j++) xl[j] = yq[j] * 0.25f;

        // ---- Gb = b @ G.T = sum_q b_q * r_q, sparse exact form ----
        float gb[8];
        {
            float h = 0.5f * bv[7];
            gb[0] = fmaf(2.0f, bv[0], -bv[1]) + h;
#pragma unroll
            for (int j = 1; j < 6; j++) gb[j] = (bv[j] - bv[j + 1]) + h;
            gb[6] = bv[6] + h;
            gb[7] = h;
        }

        // ---- x_i = Gb - 4*closest_point_E8(Gb/4);  xh += 4^m * x_i ----
        float gq[8], cpv[8];
#pragma unroll
        for (int j = 0; j < 8; j++) gq[j] = gb[j] * 0.25f;
        cp_e8(gq, cpv);

        float sc = (m == 0) ? 1.0f : (m == 1 ? 4.0f : 16.0f);
#pragma unroll
        for (int j = 0; j < 8; j++) {
            float xi = fmaf(-4.0f, cpv[j], gb[j]);   // exact dyadic == Gb - 4*cp
            if (m == 0) xh[j] = xi;
            else        xh[j] = fmaf(sc, xi, xh[j]); // exact accumulation
        }
    }

    float4 o0, o1;
    o0.x = beta * xh[0]; o0.y = beta * xh[1]; o0.z = beta * xh[2]; o0.w = beta * xh[3];
    o1.x = beta * xh[4]; o1.y = beta * xh[5]; o1.z = beta * xh[6]; o1.w = beta * xh[7];
    ((float4*)out)[2 * i]     = o0;
    ((float4*)out)[2 * i + 1] = o1;
}

extern "C" void kernel_launch(void* const* d_in, const int* in_sizes, int n_in,
                              void* d_out, int out_size) {
    const float* x    = (const float*)d_in[0];
    const float* beta = (const float*)d_in[1];
    const float* eps  = (const float*)d_in[4];
    float* out = (float*)d_out;

    int N = in_sizes[0] / 8;
    int threads = 128;
    int blocks = (N + threads - 1) / threads;
    LatticeQuantizer_kernel<<<blocks, threads>>>(x, beta, eps, out, N);
}